// round 1
// baseline (speedup 1.0000x reference)
#include <cuda_runtime.h>

#define D 128
#define H 128
#define RPB 4          // rows per block in prep kernel
#define LN_EPS 1e-3f

// ---------------- scratch (device globals; no allocation) ----------------
__device__ float  g_dA[1024 * 128];     // A = relu(seq@Ws+bs)@Wm
__device__ float  g_dB[512 * 128];      // B = relu(col@Wc+bc)@Wm + bm
__device__ float4 g_rStat[1024];        // {sum, sumsq, dot_g, 0} per position row
__device__ float4 g_cStat[512];         // same per column row
__device__ float  g_rowInv[1024];       // 1 / rowsum(exp)
__device__ float  g_segInv[64 * 512];   // 1 / segsum(exp)  [n_seq, n_col]
__device__ int    g_segId[1024];
__device__ int    g_segOff[65];
__device__ float  g_g[128];             // gamma * Wo
__device__ float  g_G;                  // sum(g)
__device__ float  g_C0;                 // beta.Wo + bo

// ---------------- kernel 1: scalars + segment ids ----------------
__global__ void k_small(const float* __restrict__ gamma, const float* __restrict__ beta,
                        const float* __restrict__ Wo, const float* __restrict__ bo,
                        const int* __restrict__ lens, int n_seq, int n_pos) {
    int t = threadIdx.x;  // 128 threads
    float gv = gamma[t] * Wo[t];
    g_g[t] = gv;
    float cb = beta[t] * Wo[t];

    __shared__ float sg[4], sc[4];
    float a = gv, b = cb;
    for (int o = 16; o > 0; o >>= 1) {
        a += __shfl_down_sync(0xFFFFFFFFu, a, o);
        b += __shfl_down_sync(0xFFFFFFFFu, b, o);
    }
    if ((t & 31) == 0) { sg[t >> 5] = a; sc[t >> 5] = b; }

    __shared__ int soff[65];
    __syncthreads();
    if (t == 0) {
        g_G  = sg[0] + sg[1] + sg[2] + sg[3];
        g_C0 = sc[0] + sc[1] + sc[2] + sc[3] + bo[0];
        int acc = 0;
        for (int s = 0; s < n_seq; s++) { soff[s] = acc; acc += lens[s]; }
        soff[n_seq] = acc;
    }
    __syncthreads();
    if (t <= n_seq) g_segOff[t] = soff[t];
    for (int p = t; p < n_pos; p += blockDim.x) {
        int s = 0;
        while (s + 1 < n_seq && p >= soff[s + 1]) s++;
        g_segId[p] = s;
    }
}

// ---------------- kernel 2: fused two-layer row precompute + stats ----------------
__global__ void k_prep(const float* __restrict__ seqf, const float* __restrict__ colf,
                       const float* __restrict__ Ws, const float* __restrict__ bs,
                       const float* __restrict__ Wc, const float* __restrict__ bc,
                       const float* __restrict__ Wm, const float* __restrict__ bm,
                       int n_pos, int n_col) {
    int h = threadIdx.x;               // 128 threads = one output feature each
    int nRowBlocks = n_pos / RPB;
    bool isCol = (int)blockIdx.x >= nRowBlocks;
    int r0 = (isCol ? (int)blockIdx.x - nRowBlocks : (int)blockIdx.x) * RPB;

    const float* feat = (isCol ? colf : seqf) + (size_t)r0 * D;
    const float* W1   = isCol ? Wc : Ws;
    const float* b1   = isCol ? bc : bs;

    __shared__ float f[RPB][D];
    __shared__ float v[RPB][D];

    #pragma unroll
    for (int r = 0; r < RPB; r++) f[r][h] = feat[r * D + h];
    __syncthreads();

    float acc[RPB];
    float bb = b1[h];
    #pragma unroll
    for (int r = 0; r < RPB; r++) acc[r] = bb;
    #pragma unroll 8
    for (int k = 0; k < D; k++) {
        float w = W1[k * H + h];
        #pragma unroll
        for (int r = 0; r < RPB; r++) acc[r] = fmaf(f[r][k], w, acc[r]);
    }
    #pragma unroll
    for (int r = 0; r < RPB; r++) v[r][h] = fmaxf(acc[r], 0.f);
    __syncthreads();

    float bmh = isCol ? bm[h] : 0.f;
    #pragma unroll
    for (int r = 0; r < RPB; r++) acc[r] = bmh;
    #pragma unroll 8
    for (int k = 0; k < H; k++) {
        float w = Wm[k * H + h];
        #pragma unroll
        for (int r = 0; r < RPB; r++) acc[r] = fmaf(v[r][k], w, acc[r]);
    }

    float* dst = (isCol ? g_dB : g_dA) + (size_t)r0 * H;
    float gh = g_g[h];

    __shared__ float su[RPB][4], sq[RPB][4], sw[RPB][4];
    #pragma unroll
    for (int r = 0; r < RPB; r++) {
        float u = acc[r];
        dst[r * H + h] = u;
        float a = u, b = u * u, c = u * gh;
        for (int o = 16; o > 0; o >>= 1) {
            a += __shfl_down_sync(0xFFFFFFFFu, a, o);
            b += __shfl_down_sync(0xFFFFFFFFu, b, o);
            c += __shfl_down_sync(0xFFFFFFFFu, c, o);
        }
        if ((h & 31) == 0) { su[r][h >> 5] = a; sq[r][h >> 5] = b; sw[r][h >> 5] = c; }
    }
    __syncthreads();
    if (h < RPB) {
        int r = h;
        float4 st;
        st.x = su[r][0] + su[r][1] + su[r][2] + su[r][3];
        st.y = sq[r][0] + sq[r][1] + sq[r][2] + sq[r][3];
        st.z = sw[r][0] + sw[r][1] + sw[r][2] + sw[r][3];
        st.w = 0.f;
        if (isCol) g_cStat[r0 + r] = st; else g_rStat[r0 + r] = st;
    }
}

// ---------------- kernel 3: 64x64 GEMM + closed-form LN + exp ----------------
__global__ void k_gemm(float* __restrict__ E, int n_pos, int n_col) {
    const int tid = threadIdx.x;           // 256
    const int tx = tid & 15, ty = tid >> 4;
    const int m0 = blockIdx.y * 64, n0 = blockIdx.x * 64;

    __shared__ float As[64][68];   // [k][m]
    __shared__ float Bs[64][68];   // [k][n]

    float acc[4][4];
    #pragma unroll
    for (int i = 0; i < 4; i++)
        #pragma unroll
        for (int j = 0; j < 4; j++) acc[i][j] = 0.f;

    for (int kc = 0; kc < H; kc += 64) {
        #pragma unroll
        for (int i = 0; i < 16; i++) {
            int lin = tid + i * 256;
            int m = lin >> 6, k = lin & 63;
            As[k][m] = g_dA[(size_t)(m0 + m) * H + kc + k];
            Bs[k][m] = g_dB[(size_t)(n0 + m) * H + kc + k];
        }
        __syncthreads();
        #pragma unroll 16
        for (int k = 0; k < 64; k++) {
            float4 a = *(const float4*)&As[k][ty * 4];
            float4 b = *(const float4*)&Bs[k][tx * 4];
            acc[0][0] = fmaf(a.x, b.x, acc[0][0]); acc[0][1] = fmaf(a.x, b.y, acc[0][1]);
            acc[0][2] = fmaf(a.x, b.z, acc[0][2]); acc[0][3] = fmaf(a.x, b.w, acc[0][3]);
            acc[1][0] = fmaf(a.y, b.x, acc[1][0]); acc[1][1] = fmaf(a.y, b.y, acc[1][1]);
            acc[1][2] = fmaf(a.y, b.z, acc[1][2]); acc[1][3] = fmaf(a.y, b.w, acc[1][3]);
            acc[2][0] = fmaf(a.z, b.x, acc[2][0]); acc[2][1] = fmaf(a.z, b.y, acc[2][1]);
            acc[2][2] = fmaf(a.z, b.z, acc[2][2]); acc[2][3] = fmaf(a.z, b.w, acc[2][3]);
            acc[3][0] = fmaf(a.w, b.x, acc[3][0]); acc[3][1] = fmaf(a.w, b.y, acc[3][1]);
            acc[3][2] = fmaf(a.w, b.z, acc[3][2]); acc[3][3] = fmaf(a.w, b.w, acc[3][3]);
        }
        __syncthreads();
    }

    const float G = g_G, C0 = g_C0;
    float4 rs[4], cs[4];
    #pragma unroll
    for (int i = 0; i < 4; i++) rs[i] = g_rStat[m0 + ty * 4 + i];
    #pragma unroll
    for (int j = 0; j < 4; j++) cs[j] = g_cStat[n0 + tx * 4 + j];

    #pragma unroll
    for (int i = 0; i < 4; i++) {
        float4 eo;
        float out[4];
        #pragma unroll
        for (int j = 0; j < 4; j++) {
            float dot = acc[i][j];
            float S1 = rs[i].x + cs[j].x;
            float mu = S1 * (1.0f / H);
            float var = (rs[i].y + 2.f * dot + cs[j].y) * (1.0f / H) - mu * mu;
            float inv = rsqrtf(var + LN_EPS);
            float raw = fmaf(rs[i].z + cs[j].z - mu * G, inv, C0);
            out[j] = expf(raw);
        }
        eo.x = out[0]; eo.y = out[1]; eo.z = out[2]; eo.w = out[3];
        *(float4*)&E[(size_t)(m0 + ty * 4 + i) * n_col + n0 + tx * 4] = eo;
    }
}

// ---------------- kernel 4: row softmax denominators ----------------
__global__ void k_rowsum(const float* __restrict__ E, int n_col) {
    int r = blockIdx.x;
    int t = threadIdx.x;  // 128
    float s = 0.f;
    for (int c = t; c < n_col; c += 128) s += E[(size_t)r * n_col + c];
    __shared__ float sm[4];
    for (int o = 16; o > 0; o >>= 1) s += __shfl_down_sync(0xFFFFFFFFu, s, o);
    if ((t & 31) == 0) sm[t >> 5] = s;
    __syncthreads();
    if (t == 0) g_rowInv[r] = 1.0f / (sm[0] + sm[1] + sm[2] + sm[3]);
}

// ---------------- kernel 5: segment sums over positions ----------------
__global__ void k_seg(const float* __restrict__ E, int n_col) {
    int s = blockIdx.y;
    int c = blockIdx.x * 128 + threadIdx.x;
    if (c >= n_col) return;
    int p0 = g_segOff[s], p1 = g_segOff[s + 1];
    float acc = 0.f;
    for (int p = p0; p < p1; p++) acc += E[(size_t)p * n_col + c];
    g_segInv[s * n_col + c] = 1.0f / acc;
}

// ---------------- kernel 6: out = Mc + Ms - Mc*Ms (in place) ----------------
__global__ void k_final(float* __restrict__ E, int n_pos, int n_col) {
    int idx = blockIdx.x * blockDim.x + threadIdx.x;   // over float4 elements
    int nc4 = n_col >> 2;
    int total = n_pos * nc4;
    if (idx >= total) return;
    int p = idx / nc4;
    int c4 = idx - p * nc4;
    float Rinv = g_rowInv[p];
    int s = g_segId[p];
    float4 e = ((const float4*)E)[idx];
    float4 Si = *(const float4*)&g_segInv[s * n_col + c4 * 4];
    float4 o;
    o.x = e.x * Rinv + e.x * Si.x - e.x * e.x * Rinv * Si.x;
    o.y = e.y * Rinv + e.y * Si.y - e.y * e.y * Rinv * Si.y;
    o.z = e.z * Rinv + e.z * Si.z - e.z * e.z * Rinv * Si.z;
    o.w = e.w * Rinv + e.w * Si.w - e.w * e.w * Rinv * Si.w;
    ((float4*)E)[idx] = o;
}

// ---------------- host launcher ----------------
extern "C" void kernel_launch(void* const* d_in, const int* in_sizes, int n_in,
                              void* d_out, int out_size) {
    const float* seqf  = (const float*)d_in[0];
    const float* colf  = (const float*)d_in[1];
    const int*   lens  = (const int*)  d_in[2];
    const float* Ws    = (const float*)d_in[3];
    const float* bs    = (const float*)d_in[4];
    const float* Wc    = (const float*)d_in[5];
    const float* bc    = (const float*)d_in[6];
    const float* Wm    = (const float*)d_in[7];
    const float* bm    = (const float*)d_in[8];
    const float* gamma = (const float*)d_in[9];
    const float* beta  = (const float*)d_in[10];
    const float* Wo    = (const float*)d_in[11];
    const float* bo    = (const float*)d_in[12];

    int n_seq = in_sizes[2];
    int n_pos = in_sizes[0] / D;   // 1024
    int n_col = in_sizes[1] / D;   // 512
    float* E = (float*)d_out;

    k_small<<<1, 128>>>(gamma, beta, Wo, bo, lens, n_seq, n_pos);
    k_prep<<<(n_pos + n_col) / RPB, 128>>>(seqf, colf, Ws, bs, Wc, bc, Wm, bm, n_pos, n_col);
    dim3 gg(n_col / 64, n_pos / 64);
    k_gemm<<<gg, 256>>>(E, n_pos, n_col);
    k_rowsum<<<n_pos, 128>>>(E, n_col);
    dim3 gs((n_col + 127) / 128, n_seq);
    k_seg<<<gs, 128>>>(E, n_col);
    int tot4 = n_pos * (n_col / 4);
    k_final<<<(tot4 + 255) / 256, 256>>>(E, n_pos, n_col);
}

// round 2
// speedup vs baseline: 1.0189x; 1.0189x over previous
#include <cuda_runtime.h>

#define D 128
#define H 128
#define RPB 4          // rows per block in prep kernel
#define LN_EPS 1e-3f

// ---------------- scratch (device globals; no allocation) ----------------
__device__ float  g_dA[1024 * 128];     // A = relu(seq@Ws+bs)@Wm
__device__ float  g_dB[512 * 128];      // B = relu(col@Wc+bc)@Wm + bm
__device__ float4 g_rStat[1024];        // {sum, sumsq, dot_g, 0} per position row
__device__ float4 g_cStat[512];         // same per column row
__device__ float  g_rowSum[1024];       // rowsum(exp)  (atomic accum)
__device__ float  g_segSum[64 * 512];   // segsum(exp)  [n_seq, n_col] (atomic accum)
__device__ int    g_segId[1024];
__device__ float  g_g[128];             // gamma * Wo
__device__ float  g_G;                  // sum(g)
__device__ float  g_C0;                 // beta.Wo + bo

// ---------------- kernel 1: scalars + segment ids + zero accumulators ----------------
__global__ void k_small(const float* __restrict__ gamma, const float* __restrict__ beta,
                        const float* __restrict__ Wo, const float* __restrict__ bo,
                        const int* __restrict__ lens, int n_seq, int n_pos, int n_col) {
    int t = threadIdx.x;  // 128 threads
    float gv = gamma[t] * Wo[t];
    g_g[t] = gv;
    float cb = beta[t] * Wo[t];

    __shared__ float sg[4], sc[4];
    float a = gv, b = cb;
    for (int o = 16; o > 0; o >>= 1) {
        a += __shfl_down_sync(0xFFFFFFFFu, a, o);
        b += __shfl_down_sync(0xFFFFFFFFu, b, o);
    }
    if ((t & 31) == 0) { sg[t >> 5] = a; sc[t >> 5] = b; }

    __shared__ int soff[65];
    __syncthreads();
    if (t == 0) {
        g_G  = sg[0] + sg[1] + sg[2] + sg[3];
        g_C0 = sc[0] + sc[1] + sc[2] + sc[3] + bo[0];
        int acc = 0;
        for (int s = 0; s < n_seq; s++) { soff[s] = acc; acc += lens[s]; }
        soff[n_seq] = acc;
    }
    __syncthreads();
    for (int p = t; p < n_pos; p += blockDim.x) {
        int s = 0;
        while (s + 1 < n_seq && p >= soff[s + 1]) s++;
        g_segId[p] = s;
    }
    // zero the atomic accumulators (graph replays rerun this every call)
    for (int i = t; i < n_pos; i += blockDim.x) g_rowSum[i] = 0.f;
    int nseg = n_seq * n_col;
    for (int i = t; i < nseg; i += blockDim.x) g_segSum[i] = 0.f;
}

// ---------------- kernel 2: fused two-layer row precompute + stats ----------------
__global__ void k_prep(const float* __restrict__ seqf, const float* __restrict__ colf,
                       const float* __restrict__ Ws, const float* __restrict__ bs,
                       const float* __restrict__ Wc, const float* __restrict__ bc,
                       const float* __restrict__ Wm, const float* __restrict__ bm,
                       int n_pos, int n_col) {
    int h = threadIdx.x;               // 128 threads = one output feature each
    int nRowBlocks = n_pos / RPB;
    bool isCol = (int)blockIdx.x >= nRowBlocks;
    int r0 = (isCol ? (int)blockIdx.x - nRowBlocks : (int)blockIdx.x) * RPB;

    const float* feat = (isCol ? colf : seqf) + (size_t)r0 * D;
    const float* W1   = isCol ? Wc : Ws;
    const float* b1   = isCol ? bc : bs;

    __shared__ float f[RPB][D];
    __shared__ float v[RPB][D];

    #pragma unroll
    for (int r = 0; r < RPB; r++) f[r][h] = feat[r * D + h];
    __syncthreads();

    float acc[RPB];
    float bb = b1[h];
    #pragma unroll
    for (int r = 0; r < RPB; r++) acc[r] = bb;
    #pragma unroll 8
    for (int k = 0; k < D; k++) {
        float w = W1[k * H + h];
        #pragma unroll
        for (int r = 0; r < RPB; r++) acc[r] = fmaf(f[r][k], w, acc[r]);
    }
    #pragma unroll
    for (int r = 0; r < RPB; r++) v[r][h] = fmaxf(acc[r], 0.f);
    __syncthreads();

    float bmh = isCol ? bm[h] : 0.f;
    #pragma unroll
    for (int r = 0; r < RPB; r++) acc[r] = bmh;
    #pragma unroll 8
    for (int k = 0; k < H; k++) {
        float w = Wm[k * H + h];
        #pragma unroll
        for (int r = 0; r < RPB; r++) acc[r] = fmaf(v[r][k], w, acc[r]);
    }

    float* dst = (isCol ? g_dB : g_dA) + (size_t)r0 * H;
    float gh = g_g[h];

    __shared__ float su[RPB][4], sq[RPB][4], sw[RPB][4];
    #pragma unroll
    for (int r = 0; r < RPB; r++) {
        float u = acc[r];
        dst[r * H + h] = u;
        float a = u, b = u * u, c = u * gh;
        for (int o = 16; o > 0; o >>= 1) {
            a += __shfl_down_sync(0xFFFFFFFFu, a, o);
            b += __shfl_down_sync(0xFFFFFFFFu, b, o);
            c += __shfl_down_sync(0xFFFFFFFFu, c, o);
        }
        if ((h & 31) == 0) { su[r][h >> 5] = a; sq[r][h >> 5] = b; sw[r][h >> 5] = c; }
    }
    __syncthreads();
    if (h < RPB) {
        int r = h;
        float4 st;
        st.x = su[r][0] + su[r][1] + su[r][2] + su[r][3];
        st.y = sq[r][0] + sq[r][1] + sq[r][2] + sq[r][3];
        st.z = sw[r][0] + sw[r][1] + sw[r][2] + sw[r][3];
        st.w = 0.f;
        if (isCol) g_cStat[r0 + r] = st; else g_rStat[r0 + r] = st;
    }
}

// ---------------- kernel 3: 64x64 GEMM + LN closed form + exp + fused sums ----------------
__global__ void k_gemm(float* __restrict__ E, int n_pos, int n_col) {
    const int tid = threadIdx.x;           // 256
    const int tx = tid & 15, ty = tid >> 4;
    const int m0 = blockIdx.y * 64, n0 = blockIdx.x * 64;

    __shared__ float As[64][68];   // [k][m]
    __shared__ float Bs[64][68];   // [k][n]
    __shared__ float colAcc[64];

    float acc[4][4];
    #pragma unroll
    for (int i = 0; i < 4; i++)
        #pragma unroll
        for (int j = 0; j < 4; j++) acc[i][j] = 0.f;

    for (int kc = 0; kc < H; kc += 64) {
        #pragma unroll
        for (int i = 0; i < 16; i++) {
            int lin = tid + i * 256;
            int m = lin >> 6, k = lin & 63;
            As[k][m] = g_dA[(size_t)(m0 + m) * H + kc + k];
            Bs[k][m] = g_dB[(size_t)(n0 + m) * H + kc + k];
        }
        __syncthreads();
        #pragma unroll 16
        for (int k = 0; k < 64; k++) {
            float4 a = *(const float4*)&As[k][ty * 4];
            float4 b = *(const float4*)&Bs[k][tx * 4];
            acc[0][0] = fmaf(a.x, b.x, acc[0][0]); acc[0][1] = fmaf(a.x, b.y, acc[0][1]);
            acc[0][2] = fmaf(a.x, b.z, acc[0][2]); acc[0][3] = fmaf(a.x, b.w, acc[0][3]);
            acc[1][0] = fmaf(a.y, b.x, acc[1][0]); acc[1][1] = fmaf(a.y, b.y, acc[1][1]);
            acc[1][2] = fmaf(a.y, b.z, acc[1][2]); acc[1][3] = fmaf(a.y, b.w, acc[1][3]);
            acc[2][0] = fmaf(a.z, b.x, acc[2][0]); acc[2][1] = fmaf(a.z, b.y, acc[2][1]);
            acc[2][2] = fmaf(a.z, b.z, acc[2][2]); acc[2][3] = fmaf(a.z, b.w, acc[2][3]);
            acc[3][0] = fmaf(a.w, b.x, acc[3][0]); acc[3][1] = fmaf(a.w, b.y, acc[3][1]);
            acc[3][2] = fmaf(a.w, b.z, acc[3][2]); acc[3][3] = fmaf(a.w, b.w, acc[3][3]);
        }
        __syncthreads();
    }

    const float G = g_G, C0 = g_C0;
    float4 rs[4], cs[4];
    #pragma unroll
    for (int i = 0; i < 4; i++) rs[i] = g_rStat[m0 + ty * 4 + i];
    #pragma unroll
    for (int j = 0; j < 4; j++) cs[j] = g_cStat[n0 + tx * 4 + j];

    float rowpart[4] = {0.f, 0.f, 0.f, 0.f};
    float colpart[4] = {0.f, 0.f, 0.f, 0.f};

    #pragma unroll
    for (int i = 0; i < 4; i++) {
        #pragma unroll
        for (int j = 0; j < 4; j++) {
            float dot = acc[i][j];
            float S1 = rs[i].x + cs[j].x;
            float mu = S1 * (1.0f / H);
            float var = (rs[i].y + 2.f * dot + cs[j].y) * (1.0f / H) - mu * mu;
            float inv = rsqrtf(var + LN_EPS);
            float raw = fmaf(rs[i].z + cs[j].z - mu * G, inv, C0);
            float e = __expf(raw);
            acc[i][j] = e;               // reuse accumulator registers for exp values
            rowpart[i] += e;
            colpart[j] += e;
        }
        float4 eo;
        eo.x = acc[i][0]; eo.y = acc[i][1]; eo.z = acc[i][2]; eo.w = acc[i][3];
        *(float4*)&E[(size_t)(m0 + ty * 4 + i) * n_col + n0 + tx * 4] = eo;
    }

    // ---- fused row sums: reduce across the 16 tx lanes (contiguous within warp) ----
    #pragma unroll
    for (int i = 0; i < 4; i++) {
        float v = rowpart[i];
        #pragma unroll
        for (int o = 8; o > 0; o >>= 1) v += __shfl_down_sync(0xFFFFFFFFu, v, o, 16);
        if (tx == 0) atomicAdd(&g_rowSum[m0 + ty * 4 + i], v);
    }

    // ---- fused segment (column) sums ----
    int sA = g_segId[m0], sB = g_segId[m0 + 63];
    if (sA == sB) {
        if (tid < 64) colAcc[tid] = 0.f;
        __syncthreads();
        #pragma unroll
        for (int j = 0; j < 4; j++) atomicAdd(&colAcc[tx * 4 + j], colpart[j]);
        __syncthreads();
        if (tid < 64) atomicAdd(&g_segSum[sA * n_col + n0 + tid], colAcc[tid]);
    } else {
        // general fallback: tile straddles a segment boundary
        #pragma unroll
        for (int i = 0; i < 4; i++) {
            int s = g_segId[m0 + ty * 4 + i];
            #pragma unroll
            for (int j = 0; j < 4; j++)
                atomicAdd(&g_segSum[s * n_col + n0 + tx * 4 + j], acc[i][j]);
        }
    }
}

// ---------------- kernel 4: out = Mc + Ms - Mc*Ms (in place) ----------------
__global__ void k_final(float* __restrict__ E, int n_pos, int n_col) {
    int idx = blockIdx.x * blockDim.x + threadIdx.x;   // over float4 elements
    int nc4 = n_col >> 2;
    int total = n_pos * nc4;
    if (idx >= total) return;
    int p = idx / nc4;
    int c4 = idx - p * nc4;
    float Rinv = __frcp_rn(g_rowSum[p]);
    int s = g_segId[p];
    float4 e = ((const float4*)E)[idx];
    const float4 ss = *(const float4*)&g_segSum[s * n_col + c4 * 4];
    float4 o;
    float mcx = e.x * Rinv, msx = e.x * __frcp_rn(ss.x);
    float mcy = e.y * Rinv, msy = e.y * __frcp_rn(ss.y);
    float mcz = e.z * Rinv, msz = e.z * __frcp_rn(ss.z);
    float mcw = e.w * Rinv, msw = e.w * __frcp_rn(ss.w);
    o.x = mcx + msx - mcx * msx;
    o.y = mcy + msy - mcy * msy;
    o.z = mcz + msz - mcz * msz;
    o.w = mcw + msw - mcw * msw;
    ((float4*)E)[idx] = o;
}

// ---------------- host launcher ----------------
extern "C" void kernel_launch(void* const* d_in, const int* in_sizes, int n_in,
                              void* d_out, int out_size) {
    const float* seqf  = (const float*)d_in[0];
    const float* colf  = (const float*)d_in[1];
    const int*   lens  = (const int*)  d_in[2];
    const float* Ws    = (const float*)d_in[3];
    const float* bs    = (const float*)d_in[4];
    const float* Wc    = (const float*)d_in[5];
    const float* bc    = (const float*)d_in[6];
    const float* Wm    = (const float*)d_in[7];
    const float* bm    = (const float*)d_in[8];
    const float* gamma = (const float*)d_in[9];
    const float* beta  = (const float*)d_in[10];
    const float* Wo    = (const float*)d_in[11];
    const float* bo    = (const float*)d_in[12];

    int n_seq = in_sizes[2];
    int n_pos = in_sizes[0] / D;   // 1024
    int n_col = in_sizes[1] / D;   // 512
    float* E = (float*)d_out;

    k_small<<<1, 128>>>(gamma, beta, Wo, bo, lens, n_seq, n_pos, n_col);
    k_prep<<<(n_pos + n_col) / RPB, 128>>>(seqf, colf, Ws, bs, Wc, bc, Wm, bm, n_pos, n_col);
    dim3 gg(n_col / 64, n_pos / 64);
    k_gemm<<<gg, 256>>>(E, n_pos, n_col);
    int tot4 = n_pos * (n_col / 4);
    k_final<<<(tot4 + 255) / 256, 256>>>(E, n_pos, n_col);
}

// round 3
// speedup vs baseline: 1.1935x; 1.1713x over previous
#include <cuda_runtime.h>

#define D 128
#define H 128
#define RPB 4
#define LN_EPS 1e-3f

// ---------------- scratch (device globals; no allocation) ----------------
__device__ float    g_dA[1024 * 128];     // A = relu(seq@Ws+bs)@Wm
__device__ float    g_dB[512 * 128];      // B = relu(col@Wc+bc)@Wm + bm
__device__ float4   g_rStat[1024];        // {sum, sumsq, dot_g, 0} per position row
__device__ float4   g_cStat[512];         // same per column row
__device__ float    g_rowSum[1024];       // rowsum(exp)  (atomic accum)
__device__ float    g_segSum[64 * 512];   // segsum(exp)  [n_seq, n_col] (atomic accum)
__device__ int      g_segId[1024];
__device__ float    g_G;                  // sum(gamma*Wo)
__device__ float    g_C0;                 // beta.Wo + bo
__device__ unsigned g_bar;                // grid barrier counter (zeroed by K1)

// ---------------- kernel 1: prep (8 rows/block) + scalars + zeroing ----------------
__global__ void __launch_bounds__(256)
k_prep(const float* __restrict__ seqf, const float* __restrict__ colf,
       const float* __restrict__ Ws, const float* __restrict__ bs,
       const float* __restrict__ Wc, const float* __restrict__ bc,
       const float* __restrict__ Wm, const float* __restrict__ bm,
       const float* __restrict__ gamma, const float* __restrict__ beta,
       const float* __restrict__ Wo, const float* __restrict__ bo,
       const int* __restrict__ lens,
       int n_pos, int n_col, int n_seq) {
    const int tid = threadIdx.x;           // 256
    const int sub = tid >> 7;              // 0/1 : two 4-row subunits
    const int h   = tid & 127;

    // ---- zero atomic accumulators + barrier counter (spread across grid) ----
    {
        int total = n_pos + n_seq * n_col;
        for (int i = blockIdx.x * 256 + tid; i < total; i += gridDim.x * 256) {
            if (i < n_pos) g_rowSum[i] = 0.f;
            else           g_segSum[i - n_pos] = 0.f;
        }
        if (blockIdx.x == 0 && tid == 0) g_bar = 0u;
    }

    // ---- fused two-layer row precompute ----
    int rowBase = blockIdx.x * (2 * RPB) + sub * RPB;
    bool isCol = rowBase >= n_pos;
    int r0 = isCol ? rowBase - n_pos : rowBase;

    const float* feat = (isCol ? colf : seqf) + (size_t)r0 * D;
    const float* W1   = isCol ? Wc : Ws;
    const float* b1   = isCol ? bc : bs;

    __shared__ float f[2][RPB][D];
    __shared__ float v[2][RPB][D];
    __shared__ float su[2][RPB][4], sq[2][RPB][4], sw[2][RPB][4];

    #pragma unroll
    for (int r = 0; r < RPB; r++) f[sub][r][h] = feat[r * D + h];
    __syncthreads();

    float acc[RPB];
    float bb = b1[h];
    #pragma unroll
    for (int r = 0; r < RPB; r++) acc[r] = bb;
    #pragma unroll 8
    for (int k = 0; k < D; k++) {
        float w = W1[k * H + h];
        #pragma unroll
        for (int r = 0; r < RPB; r++) acc[r] = fmaf(f[sub][r][k], w, acc[r]);
    }
    #pragma unroll
    for (int r = 0; r < RPB; r++) v[sub][r][h] = fmaxf(acc[r], 0.f);
    __syncthreads();

    float bmh = isCol ? bm[h] : 0.f;
    #pragma unroll
    for (int r = 0; r < RPB; r++) acc[r] = bmh;
    #pragma unroll 8
    for (int k = 0; k < H; k++) {
        float w = Wm[k * H + h];
        #pragma unroll
        for (int r = 0; r < RPB; r++) acc[r] = fmaf(v[sub][r][k], w, acc[r]);
    }

    float* dst = (isCol ? g_dB : g_dA) + (size_t)r0 * H;
    float gh = gamma[h] * Wo[h];

    #pragma unroll
    for (int r = 0; r < RPB; r++) {
        float u = acc[r];
        dst[r * H + h] = u;
        float a = u, b = u * u, c = u * gh;
        for (int o = 16; o > 0; o >>= 1) {
            a += __shfl_down_sync(0xFFFFFFFFu, a, o);
            b += __shfl_down_sync(0xFFFFFFFFu, b, o);
            c += __shfl_down_sync(0xFFFFFFFFu, c, o);
        }
        if ((h & 31) == 0) { su[sub][r][h >> 5] = a; sq[sub][r][h >> 5] = b; sw[sub][r][h >> 5] = c; }
    }
    __syncthreads();
    if (h < RPB) {
        int r = h;
        float4 st;
        st.x = su[sub][r][0] + su[sub][r][1] + su[sub][r][2] + su[sub][r][3];
        st.y = sq[sub][r][0] + sq[sub][r][1] + sq[sub][r][2] + sq[sub][r][3];
        st.z = sw[sub][r][0] + sw[sub][r][1] + sw[sub][r][2] + sw[sub][r][3];
        st.w = 0.f;
        if (isCol) g_cStat[r0 + r] = st; else g_rStat[r0 + r] = st;
    }

    // ---- block 0: scalars + segment ids ----
    if (blockIdx.x == 0) {
        __shared__ float sg[4], sc[4];
        __shared__ int soff[65];
        if (tid < 128) {
            float a = gamma[tid] * Wo[tid];
            float b = beta[tid] * Wo[tid];
            for (int o = 16; o > 0; o >>= 1) {
                a += __shfl_down_sync(0xFFFFFFFFu, a, o);
                b += __shfl_down_sync(0xFFFFFFFFu, b, o);
            }
            if ((tid & 31) == 0) { sg[tid >> 5] = a; sc[tid >> 5] = b; }
        }
        __syncthreads();
        if (tid == 0) {
            g_G  = sg[0] + sg[1] + sg[2] + sg[3];
            g_C0 = sc[0] + sc[1] + sc[2] + sc[3] + bo[0];
            int acc2 = 0;
            for (int s = 0; s < n_seq; s++) { soff[s] = acc2; acc2 += lens[s]; }
            soff[n_seq] = acc2;
        }
        __syncthreads();
        for (int p = tid; p < n_pos; p += 256) {
            int s = 0;
            while (s + 1 < n_seq && p >= soff[s + 1]) s++;
            g_segId[p] = s;
        }
    }
}

// ---------------- kernel 2: GEMM + LN + exp + sums + grid barrier + finalize ----------------
__global__ void __launch_bounds__(256, 1)
k_gemm(float* __restrict__ E, int n_pos, int n_col, int nblk) {
    const int tid = threadIdx.x;           // 256
    const int tx = tid & 15, ty = tid >> 4;
    const int m0 = blockIdx.y * 64, n0 = blockIdx.x * 64;

    __shared__ float As[64][68];   // [k][m]
    __shared__ float Bs[64][68];   // [k][n]
    __shared__ float colAcc[64];

    float acc[4][4];
    #pragma unroll
    for (int i = 0; i < 4; i++)
        #pragma unroll
        for (int j = 0; j < 4; j++) acc[i][j] = 0.f;

    for (int kc = 0; kc < H; kc += 64) {
        #pragma unroll
        for (int i = 0; i < 16; i++) {
            int lin = tid + i * 256;
            int m = lin >> 6, k = lin & 63;
            As[k][m] = g_dA[(size_t)(m0 + m) * H + kc + k];
            Bs[k][m] = g_dB[(size_t)(n0 + m) * H + kc + k];
        }
        __syncthreads();
        #pragma unroll 16
        for (int k = 0; k < 64; k++) {
            float4 a = *(const float4*)&As[k][ty * 4];
            float4 b = *(const float4*)&Bs[k][tx * 4];
            acc[0][0] = fmaf(a.x, b.x, acc[0][0]); acc[0][1] = fmaf(a.x, b.y, acc[0][1]);
            acc[0][2] = fmaf(a.x, b.z, acc[0][2]); acc[0][3] = fmaf(a.x, b.w, acc[0][3]);
            acc[1][0] = fmaf(a.y, b.x, acc[1][0]); acc[1][1] = fmaf(a.y, b.y, acc[1][1]);
            acc[1][2] = fmaf(a.y, b.z, acc[1][2]); acc[1][3] = fmaf(a.y, b.w, acc[1][3]);
            acc[2][0] = fmaf(a.z, b.x, acc[2][0]); acc[2][1] = fmaf(a.z, b.y, acc[2][1]);
            acc[2][2] = fmaf(a.z, b.z, acc[2][2]); acc[2][3] = fmaf(a.z, b.w, acc[2][3]);
            acc[3][0] = fmaf(a.w, b.x, acc[3][0]); acc[3][1] = fmaf(a.w, b.y, acc[3][1]);
            acc[3][2] = fmaf(a.w, b.z, acc[3][2]); acc[3][3] = fmaf(a.w, b.w, acc[3][3]);
        }
        __syncthreads();
    }

    const float G = g_G, C0 = g_C0;
    float4 rs[4], cs[4];
    #pragma unroll
    for (int i = 0; i < 4; i++) rs[i] = g_rStat[m0 + ty * 4 + i];
    #pragma unroll
    for (int j = 0; j < 4; j++) cs[j] = g_cStat[n0 + tx * 4 + j];

    float rowpart[4] = {0.f, 0.f, 0.f, 0.f};
    float colpart[4] = {0.f, 0.f, 0.f, 0.f};

    #pragma unroll
    for (int i = 0; i < 4; i++) {
        #pragma unroll
        for (int j = 0; j < 4; j++) {
            float dot = acc[i][j];
            float S1 = rs[i].x + cs[j].x;
            float mu = S1 * (1.0f / H);
            float var = (rs[i].y + 2.f * dot + cs[j].y) * (1.0f / H) - mu * mu;
            float inv = rsqrtf(var + LN_EPS);
            float raw = fmaf(rs[i].z + cs[j].z - mu * G, inv, C0);
            float e = __expf(raw);
            acc[i][j] = e;               // keep exp values in registers
            rowpart[i] += e;
            colpart[j] += e;
        }
    }

    // ---- fused row sums: reduce across the 16 tx lanes ----
    #pragma unroll
    for (int i = 0; i < 4; i++) {
        float v = rowpart[i];
        #pragma unroll
        for (int o = 8; o > 0; o >>= 1) v += __shfl_down_sync(0xFFFFFFFFu, v, o, 16);
        if (tx == 0) atomicAdd(&g_rowSum[m0 + ty * 4 + i], v);
    }

    // ---- fused segment (column) sums ----
    int sRow[4];
    #pragma unroll
    for (int i = 0; i < 4; i++) sRow[i] = g_segId[m0 + ty * 4 + i];
    int sA = g_segId[m0], sB = g_segId[m0 + 63];
    if (sA == sB) {
        if (tid < 64) colAcc[tid] = 0.f;
        __syncthreads();
        #pragma unroll
        for (int j = 0; j < 4; j++) atomicAdd(&colAcc[tx * 4 + j], colpart[j]);
        __syncthreads();
        if (tid < 64) atomicAdd(&g_segSum[sA * n_col + n0 + tid], colAcc[tid]);
    } else {
        #pragma unroll
        for (int i = 0; i < 4; i++) {
            #pragma unroll
            for (int j = 0; j < 4; j++)
                atomicAdd(&g_segSum[sRow[i] * n_col + n0 + tx * 4 + j], acc[i][j]);
        }
    }

    // ---- grid barrier (all 128 blocks resident in one wave) ----
    __syncthreads();
    if (tid == 0) {
        __threadfence();
        atomicAdd(&g_bar, 1u);
        while (*(volatile unsigned*)&g_bar < (unsigned)nblk) { }
    }
    __syncthreads();

    // ---- finalize: Mc + Ms - Mc*Ms, single store to output ----
    #pragma unroll
    for (int i = 0; i < 4; i++) {
        float Rinv = __frcp_rn(g_rowSum[m0 + ty * 4 + i]);
        const float4 ss = *(const float4*)&g_segSum[sRow[i] * n_col + n0 + tx * 4];
        float4 o;
        float mcx = acc[i][0] * Rinv, msx = acc[i][0] * __frcp_rn(ss.x);
        float mcy = acc[i][1] * Rinv, msy = acc[i][1] * __frcp_rn(ss.y);
        float mcz = acc[i][2] * Rinv, msz = acc[i][2] * __frcp_rn(ss.z);
        float mcw = acc[i][3] * Rinv, msw = acc[i][3] * __frcp_rn(ss.w);
        o.x = mcx + msx - mcx * msx;
        o.y = mcy + msy - mcy * msy;
        o.z = mcz + msz - mcz * msz;
        o.w = mcw + msw - mcw * msw;
        *(float4*)&E[(size_t)(m0 + ty * 4 + i) * n_col + n0 + tx * 4] = o;
    }
}

// ---------------- host launcher ----------------
extern "C" void kernel_launch(void* const* d_in, const int* in_sizes, int n_in,
                              void* d_out, int out_size) {
    const float* seqf  = (const float*)d_in[0];
    const float* colf  = (const float*)d_in[1];
    const int*   lens  = (const int*)  d_in[2];
    const float* Ws    = (const float*)d_in[3];
    const float* bs    = (const float*)d_in[4];
    const float* Wc    = (const float*)d_in[5];
    const float* bc    = (const float*)d_in[6];
    const float* Wm    = (const float*)d_in[7];
    const float* bm    = (const float*)d_in[8];
    const float* gamma = (const float*)d_in[9];
    const float* beta  = (const float*)d_in[10];
    const float* Wo    = (const float*)d_in[11];
    const float* bo    = (const float*)d_in[12];

    int n_seq = in_sizes[2];
    int n_pos = in_sizes[0] / D;   // 1024
    int n_col = in_sizes[1] / D;   // 512
    float* E = (float*)d_out;

    int g1 = (n_pos + n_col) / (2 * RPB);           // 192 blocks
    k_prep<<<g1, 256>>>(seqf, colf, Ws, bs, Wc, bc, Wm, bm,
                        gamma, beta, Wo, bo, lens, n_pos, n_col, n_seq);
    dim3 gg(n_col / 64, n_pos / 64);                // 8 x 16 = 128 blocks (single wave)
    k_gemm<<<gg, 256>>>(E, n_pos, n_col, (int)(gg.x * gg.y));
}